// round 9
// baseline (speedup 1.0000x reference)
#include <cuda_runtime.h>
#include <math.h>

#define CH   64
#define HH   256
#define WW   256
#define HWX  65536
#define NPIX (2*HWX)

typedef unsigned long long u64t;

__device__ __forceinline__ u64t pk2(float lo, float hi) {
    u64t r; asm("mov.b64 %0,{%1,%2};" : "=l"(r) : "f"(lo), "f"(hi)); return r;
}
__device__ __forceinline__ void upk2(float& lo, float& hi, u64t v) {
    asm("mov.b64 {%0,%1},%2;" : "=f"(lo), "=f"(hi) : "l"(v));
}
__device__ __forceinline__ u64t ffma2(u64t a, u64t b, u64t c) {
    u64t d; asm("fma.rn.f32x2 %0,%1,%2,%3;" : "=l"(d) : "l"(a), "l"(b), "l"(c)); return d;
}
__device__ __forceinline__ u64t fmul2(u64t a, u64t b) {
    u64t d; asm("mul.rn.f32x2 %0,%1,%2;" : "=l"(d) : "l"(a), "l"(b)); return d;
}

// Precomputed-constant buffer layout (floats) in d_const
#define OFF_QWS  0        // [c][o] folded q weights        (4096)
#define OFF_KWS  4096     // [c][o] folded k weights        (4096)
#define OFF_VWS  8192     // [c][o] folded v weights        (4096)
#define OFF_QWPE 12288    // [j][t4][o] PE-rearranged q_w   (8192)
#define OFF_KB   20480    // [uv][o] k pe-bias              (256)
#define OFF_VB   20736    // [uv][o] v pe-bias              (256)
#define OFF_QB   20992    // q bias                          (64)
#define OFF_FREQ 21056    // 10000^(-j/32)                   (32)
#define NCONST   21088

__device__ float d_const[NCONST];
__device__ float q_scr[64 * NPIX];   // q scratch, [o][pix]
__device__ float suppT[64 * NPIX];   // pixel-major support features [b][hw][c]

// Q-kernel smem layout (floats)
#define QS_QWS  0
#define QS_QWPE 4096
#define QS_QB   12288
#define QS_FREQ 12352
#define QS_N    12384     // 49536 B

// AV-kernel smem layout (floats)
#define AS_KWS  0
#define AS_VWS  4096
#define AS_KB   8192
#define AS_VB   8448
#define AS_N    8704      // 34816 B

// ---------------------------------------------------------------------------
// Setup kernel: 32 blocks x 256. Bias computation: one warp per (uv,o),
// lane = frequency index j, butterfly reduction.
// ---------------------------------------------------------------------------
__global__ void iw_setup_kernel(const float* __restrict__ qw, const float* __restrict__ qb,
                                const float* __restrict__ kw, const float* __restrict__ kb,
                                const float* __restrict__ vw, const float* __restrict__ vb)
{
    const int g = blockIdx.x * 256 + threadIdx.x;      // 8192 threads total
    const float LN1E4_32 = 9.210340371976184f / 32.0f; // ln(10000)/32

    // folded weights: ws[c][o] = w[o][2c] + w[o][2c+1]
    if (g < 4096) {
        int c = g >> 6, o = g & 63;
        d_const[OFF_QWS + g] = qw[o*128 + 2*c] + qw[o*128 + 2*c + 1];
        d_const[OFF_KWS + g] = kw[o*128 + 2*c] + kw[o*128 + 2*c + 1];
        d_const[OFF_VWS + g] = vw[o*128 + 2*c] + vw[o*128 + 2*c + 1];
    }

    // PE-rearranged q weights: [j][t4][o], t4: 0=sin_y,1=cos_y,2=sin_x,3=cos_x
    {
        int j = g >> 8, r = g & 255, t4 = r >> 6, o = r & 63;
        int col = (t4 < 2) ? (2*j + t4) : (64 + 2*j + (t4 - 2));
        d_const[OFF_QWPE + g] = qw[o*128 + col];
    }

    if (g < 32) d_const[OFF_FREQ + g] = __expf(-(float)g * LN1E4_32);
    if (g < 64) d_const[OFF_QB + g]   = qb[g];

    // window-PE biases: warp W = (uv,o); lane j = frequency.
    const float SW = (float)(2.0 * M_PI / (1.0 + 1e-6));
    int W = g >> 5, j = g & 31;                        // W in [0,256)
    int uv = W >> 6, o = W & 63;
    float uu = (float)(uv >> 1), vv = (float)(uv & 1);
    float f = __expf(-(float)j * LN1E4_32);
    float syv, cyv, sxv, cxv;
    __sincosf(uu * SW * f, &syv, &cyv);
    __sincosf(vv * SW * f, &sxv, &cxv);
    float aK = syv*kw[o*128+2*j] + cyv*kw[o*128+2*j+1]
             + sxv*kw[o*128+64+2*j] + cxv*kw[o*128+64+2*j+1];
    float aV = syv*vw[o*128+2*j] + cyv*vw[o*128+2*j+1]
             + sxv*vw[o*128+64+2*j] + cxv*vw[o*128+64+2*j+1];
    #pragma unroll
    for (int s = 16; s > 0; s >>= 1) {
        aK += __shfl_xor_sync(0xffffffffu, aK, s);
        aV += __shfl_xor_sync(0xffffffffu, aV, s);
    }
    if (j == 0) {
        d_const[OFF_KB + W] = aK + kb[o];
        d_const[OFF_VB + W] = aV + vb[o];
    }
}

// ---------------------------------------------------------------------------
// Transpose kernel: supp (c-major) -> suppT (pixel-major rows of 64 floats).
// 64px x 64ch smem tile, padded to kill bank conflicts.
// ---------------------------------------------------------------------------
__global__ void __launch_bounds__(256) iw_transpose_kernel(const float* __restrict__ supp)
{
    __shared__ float t[64][65];
    int tile = blockIdx.x;                  // 2048 tiles of 64 pixels
    int gpx0 = tile * 64;
    int b    = gpx0 >> 16;
    int px0  = gpx0 & 65535;

    const float* s = supp + b*(CH*HWX) + px0;
    int lx = threadIdx.x & 63;              // pixel within tile
    int ly = threadIdx.x >> 6;              // channel start (0..3)
    #pragma unroll
    for (int c = 0; c < 64; c += 4)
        t[c + ly][lx] = s[(c + ly)*HWX + lx];
    __syncthreads();

    float* d = suppT + (size_t)gpx0 * 64;
    int cx = threadIdx.x & 63;              // channel
    int py = threadIdx.x >> 6;              // pixel start (0..3)
    #pragma unroll
    for (int p = 0; p < 64; p += 4)
        d[(p + py)*64 + cx] = t[cx][p + py];
}

__global__ void iw_dummy_kernel() {}

// ---------------------------------------------------------------------------
// Q kernel: q = folded-curr matvec + PE matvec + bias, all in packed f32x2.
// ---------------------------------------------------------------------------
__global__ void __launch_bounds__(256, 2) iw_q_kernel(
    const float* __restrict__ curr, const float* __restrict__ flow)
{
    extern __shared__ float sm[];
    for (int i = threadIdx.x; i < 4096; i += 256) sm[QS_QWS  + i] = d_const[OFF_QWS  + i];
    for (int i = threadIdx.x; i < 8192; i += 256) sm[QS_QWPE + i] = d_const[OFF_QWPE + i];
    if (threadIdx.x < 64) sm[QS_QB   + threadIdx.x] = d_const[OFF_QB   + threadIdx.x];
    if (threadIdx.x < 32) sm[QS_FREQ + threadIdx.x] = d_const[OFF_FREQ + threadIdx.x];
    __syncthreads();

    const float* s_qws  = sm + QS_QWS;
    const float* s_qwpe = sm + QS_QWPE;
    const float* s_fr   = sm + QS_FREQ;

    int pix = blockIdx.x * 256 + threadIdx.x;
    int b   = pix >> 16;
    int rem = pix & 65535;
    int yy  = rem >> 8;
    int xx  = rem & 255;

    float2 fl = reinterpret_cast<const float2*>(flow)[pix];
    float gy = (float)yy + fl.y;
    float gx = (float)xx + fl.x;
    float dy = gy - floorf(gy);
    float dx = gx - floorf(gx);

    const float* currB = curr + b*(CH*HWX) + yy*WW + xx;

    u64t q2[32];
    const u64t* qb2 = reinterpret_cast<const u64t*>(sm + QS_QB);
    #pragma unroll
    for (int i = 0; i < 32; i++) q2[i] = qb2[i];

    #pragma unroll 4
    for (int c = 0; c < 64; c++) {
        float fc = __ldg(currB + c*HWX);
        u64t fc2 = pk2(fc, fc);
        const u64t* wc2 = reinterpret_cast<const u64t*>(s_qws + c*64);
        #pragma unroll
        for (int i = 0; i < 32; i++) q2[i] = ffma2(fc2, wc2[i], q2[i]);
    }

    const float PE2 = (float)(2.0 * M_PI / (2.0 + 1e-6));  // card = (U,V) = (2,2)
    float ay = dy * PE2, ax = dx * PE2;
    #pragma unroll 2
    for (int j = 0; j < 32; j++) {
        float f = s_fr[j];
        float syv, cyv, sxv, cxv;
        __sincosf(ay * f, &syv, &cyv);
        __sincosf(ax * f, &sxv, &cxv);
        u64t sy2 = pk2(syv, syv), cy2 = pk2(cyv, cyv);
        u64t sx2 = pk2(sxv, sxv), cx2 = pk2(cxv, cxv);
        const u64t* wj2 = reinterpret_cast<const u64t*>(s_qwpe + j*256);
        #pragma unroll
        for (int i = 0; i < 32; i++) {
            u64t acc = q2[i];
            acc = ffma2(sy2, wj2[i],      acc);
            acc = ffma2(cy2, wj2[32 + i], acc);
            acc = ffma2(sx2, wj2[64 + i], acc);
            acc = ffma2(cx2, wj2[96 + i], acc);
            q2[i] = acc;
        }
    }

    #pragma unroll
    for (int i = 0; i < 32; i++) {
        float lo, hi; upk2(lo, hi, q2[i]);
        q_scr[(2*i)*NPIX + pix]     = lo;
        q_scr[(2*i + 1)*NPIX + pix] = hi;
    }
}

// ---------------------------------------------------------------------------
// AV kernel: vectorized gather (suppT rows) + attn + softmax + value pass.
// ---------------------------------------------------------------------------
__global__ void __launch_bounds__(128, 3) iw_av_kernel(
    const float* __restrict__ flow, float* __restrict__ out)
{
    extern __shared__ float sm[];
    for (int i = threadIdx.x; i < 4096; i += 128) {
        sm[AS_KWS + i] = d_const[OFF_KWS + i];
        sm[AS_VWS + i] = d_const[OFF_VWS + i];
    }
    for (int i = threadIdx.x; i < 256; i += 128) {
        sm[AS_KB + i] = d_const[OFF_KB + i];
        sm[AS_VB + i] = d_const[OFF_VB + i];
    }
    __syncthreads();

    const float* s_kws = sm + AS_KWS;
    const float* s_vws = sm + AS_VWS;
    const float* s_kb  = sm + AS_KB;
    const float* s_vb  = sm + AS_VB;

    int pix = blockIdx.x * 128 + threadIdx.x;
    int b   = pix >> 16;
    int rem = pix & 65535;
    int yy  = rem >> 8;
    int xx  = rem & 255;

    float2 fl = reinterpret_cast<const float2*>(flow)[pix];
    float gy = (float)yy + fl.y;
    float gx = (float)xx + fl.x;
    int iy = (int)floorf(gy), ix = (int)floorf(gx);
    int r0 = min(max(iy,     0), HH-1);
    int r1 = min(max(iy + 1, 0), HH-1);
    int c0 = min(max(ix,     0), WW-1);
    int c1 = min(max(ix + 1, 0), WW-1);

    const float4* r00 = reinterpret_cast<const float4*>(suppT + ((size_t)(b*HWX) + r0*WW + c0)*64);
    const float4* r01 = reinterpret_cast<const float4*>(suppT + ((size_t)(b*HWX) + r0*WW + c1)*64);
    const float4* r10 = reinterpret_cast<const float4*>(suppT + ((size_t)(b*HWX) + r1*WW + c0)*64);
    const float4* r11 = reinterpret_cast<const float4*>(suppT + ((size_t)(b*HWX) + r1*WW + c1)*64);

    // load q packed (pairs over o)
    u64t q2[32];
    #pragma unroll
    for (int i = 0; i < 32; i++)
        q2[i] = pk2(q_scr[(2*i)*NPIX + pix], q_scr[(2*i + 1)*NPIX + pix]);

    // -------- attn init: packed bias-dot q . kb[u] --------
    u64t A01[8], A23[8];
    #pragma unroll
    for (int h = 0; h < 8; h++) {
        float av[4];
        #pragma unroll
        for (int u = 0; u < 4; u++) {
            const u64t* kb2 = reinterpret_cast<const u64t*>(s_kb + u*64);
            u64t d2 = fmul2(q2[h*4], kb2[h*4]);
            d2 = ffma2(q2[h*4+1], kb2[h*4+1], d2);
            d2 = ffma2(q2[h*4+2], kb2[h*4+2], d2);
            d2 = ffma2(q2[h*4+3], kb2[h*4+3], d2);
            float lo, hi; upk2(lo, hi, d2);
            av[u] = lo + hi;
        }
        A01[h] = pk2(av[0], av[1]);
        A23[h] = pk2(av[2], av[3]);
    }

    // -------- attn logits: folded qk dot over vectorized gather --------
    for (int ch = 0; ch < 8; ch++) {
        float4 a00 = __ldg(r00 + ch*2), b00 = __ldg(r00 + ch*2 + 1);
        float4 a01 = __ldg(r01 + ch*2), b01 = __ldg(r01 + ch*2 + 1);
        float4 a10 = __ldg(r10 + ch*2), b10 = __ldg(r10 + ch*2 + 1);
        float4 a11 = __ldg(r11 + ch*2), b11 = __ldg(r11 + ch*2 + 1);
        float f00[8] = {a00.x,a00.y,a00.z,a00.w,b00.x,b00.y,b00.z,b00.w};
        float f01[8] = {a01.x,a01.y,a01.z,a01.w,b01.x,b01.y,b01.z,b01.w};
        float f10[8] = {a10.x,a10.y,a10.z,a10.w,b10.x,b10.y,b10.z,b10.w};
        float f11[8] = {a11.x,a11.y,a11.z,a11.w,b11.x,b11.y,b11.z,b11.w};
        #pragma unroll
        for (int cc = 0; cc < 8; cc++) {
            const u64t* wc2 = reinterpret_cast<const u64t*>(s_kws + (ch*8 + cc)*64);
            u64t F01 = pk2(f00[cc], f01[cc]);
            u64t F23 = pk2(f10[cc], f11[cc]);
            #pragma unroll
            for (int h = 0; h < 8; h++) {
                u64t d2 = fmul2(q2[h*4], wc2[h*4]);
                d2 = ffma2(q2[h*4+1], wc2[h*4+1], d2);
                d2 = ffma2(q2[h*4+2], wc2[h*4+2], d2);
                d2 = ffma2(q2[h*4+3], wc2[h*4+3], d2);
                float lo, hi; upk2(lo, hi, d2);
                float qk = lo + hi;
                u64t qk2 = pk2(qk, qk);
                A01[h] = ffma2(qk2, F01, A01[h]);
                A23[h] = ffma2(qk2, F23, A23[h]);
            }
        }
    }

    // -------- softmax over the 4 window positions (scale = 8^-0.5) --------
    const float SC = 0.35355339059327376f;
    float attn[8][4];
    #pragma unroll
    for (int h = 0; h < 8; h++) {
        float a0, a1, a2, a3;
        upk2(a0, a1, A01[h]);
        upk2(a2, a3, A23[h]);
        float m = fmaxf(fmaxf(a0, a1), fmaxf(a2, a3));
        float p0 = __expf((a0 - m) * SC);
        float p1 = __expf((a1 - m) * SC);
        float p2 = __expf((a2 - m) * SC);
        float p3 = __expf((a3 - m) * SC);
        float inv = __fdividef(1.0f, p0 + p1 + p2 + p3);
        attn[h][0] = p0*inv; attn[h][1] = p1*inv;
        attn[h][2] = p2*inv; attn[h][3] = p3*inv;
        A01[h] = pk2(attn[h][0], attn[h][1]);
        A23[h] = pk2(attn[h][2], attn[h][3]);
    }

    // -------- output: g-fold over second vectorized gather pass --------
    u64t out2[32];
    #pragma unroll
    for (int i = 0; i < 32; i++) out2[i] = 0ULL;

    for (int ch = 0; ch < 8; ch++) {
        float4 a00 = __ldg(r00 + ch*2), b00 = __ldg(r00 + ch*2 + 1);
        float4 a01 = __ldg(r01 + ch*2), b01 = __ldg(r01 + ch*2 + 1);
        float4 a10 = __ldg(r10 + ch*2), b10 = __ldg(r10 + ch*2 + 1);
        float4 a11 = __ldg(r11 + ch*2), b11 = __ldg(r11 + ch*2 + 1);
        float f00[8] = {a00.x,a00.y,a00.z,a00.w,b00.x,b00.y,b00.z,b00.w};
        float f01[8] = {a01.x,a01.y,a01.z,a01.w,b01.x,b01.y,b01.z,b01.w};
        float f10[8] = {a10.x,a10.y,a10.z,a10.w,b10.x,b10.y,b10.z,b10.w};
        float f11[8] = {a11.x,a11.y,a11.z,a11.w,b11.x,b11.y,b11.z,b11.w};
        #pragma unroll
        for (int cc = 0; cc < 8; cc++) {
            const u64t* wc2 = reinterpret_cast<const u64t*>(s_vws + (ch*8 + cc)*64);
            u64t F01 = pk2(f00[cc], f01[cc]);
            u64t F23 = pk2(f10[cc], f11[cc]);
            u64t gv2[8];
            #pragma unroll
            for (int h = 0; h < 8; h++) {
                u64t g2 = fmul2(A01[h], F01);
                g2 = ffma2(A23[h], F23, g2);
                float lo, hi; upk2(lo, hi, g2);
                float gv = lo + hi;
                gv2[h] = pk2(gv, gv);
            }
            #pragma unroll
            for (int i = 0; i < 32; i++)
                out2[i] = ffma2(gv2[i >> 2], wc2[i], out2[i]);
        }
    }

    // v pe-bias term + store
    float* outB = out + b*(CH*HWX) + yy*WW + xx;
    #pragma unroll
    for (int i = 0; i < 32; i++) {
        float lo, hi; upk2(lo, hi, out2[i]);
        int o0 = 2*i, o1 = 2*i + 1;
        int h = o0 >> 3;
        #pragma unroll
        for (int u = 0; u < 4; u++) {
            lo = fmaf(attn[h][u], s_vb[u*64 + o0], lo);
            hi = fmaf(attn[h][u], s_vb[u*64 + o1], hi);
        }
        outB[o0*HWX] = lo;
        outB[o1*HWX] = hi;
    }
}

// ---------------------------------------------------------------------------
extern "C" void kernel_launch(void* const* d_in, const int* in_sizes, int n_in,
                              void* d_out, int out_size)
{
    const float* supp = (const float*)d_in[0];
    const float* flow = (const float*)d_in[1];
    const float* curr = (const float*)d_in[2];
    const float* qw   = (const float*)d_in[3];
    const float* qb   = (const float*)d_in[4];
    const float* kw   = (const float*)d_in[5];
    const float* kb   = (const float*)d_in[6];
    const float* vw   = (const float*)d_in[7];
    const float* vb   = (const float*)d_in[8];
    float* outp = (float*)d_out;

    cudaFuncSetAttribute(iw_q_kernel,
                         cudaFuncAttributeMaxDynamicSharedMemorySize, QS_N * 4);
    cudaFuncSetAttribute(iw_av_kernel,
                         cudaFuncAttributeMaxDynamicSharedMemorySize, AS_N * 4);

    // 6 launches/call so ncu (-s 5 -c 1) captures the AV kernel.
    iw_setup_kernel<<<32, 256>>>(qw, qb, kw, kb, vw, vb);
    iw_transpose_kernel<<<NPIX / 64, 256>>>(supp);
    iw_q_kernel<<<NPIX / 256, 256, QS_N * 4>>>(curr, flow);
    iw_dummy_kernel<<<1, 32>>>();
    iw_dummy_kernel<<<1, 32>>>();
    iw_av_kernel<<<NPIX / 128, 128, AS_N * 4>>>(flow, outp);
}

// round 10
// speedup vs baseline: 1.1052x; 1.1052x over previous
#include <cuda_runtime.h>
#include <math.h>

#define CH   64
#define HH   256
#define WW   256
#define HWX  65536
#define NPIX (2*HWX)

typedef unsigned long long u64t;

__device__ __forceinline__ u64t pk2(float lo, float hi) {
    u64t r; asm("mov.b64 %0,{%1,%2};" : "=l"(r) : "f"(lo), "f"(hi)); return r;
}
__device__ __forceinline__ void upk2(float& lo, float& hi, u64t v) {
    asm("mov.b64 {%0,%1},%2;" : "=f"(lo), "=f"(hi) : "l"(v));
}
__device__ __forceinline__ u64t ffma2(u64t a, u64t b, u64t c) {
    u64t d; asm("fma.rn.f32x2 %0,%1,%2,%3;" : "=l"(d) : "l"(a), "l"(b), "l"(c)); return d;
}
__device__ __forceinline__ u64t fmul2(u64t a, u64t b) {
    u64t d; asm("mul.rn.f32x2 %0,%1,%2;" : "=l"(d) : "l"(a), "l"(b)); return d;
}

// Precomputed-constant buffer layout (floats) in d_const
#define OFF_QWS  0        // [c][o] folded q weights        (4096)
#define OFF_KWS  4096     // [c][o] folded k weights        (4096)
#define OFF_VWS  8192     // [c][o] folded v weights        (4096)
#define OFF_QWPE 12288    // [j][t4][o] PE-rearranged q_w   (8192)
#define OFF_KB   20480    // [uv][o] k pe-bias              (256)
#define OFF_VB   20736    // [uv][o] v pe-bias              (256)
#define OFF_QB   20992    // q bias                          (64)
#define OFF_FREQ 21056    // 10000^(-j/32)                   (32)
#define NCONST   21088

__device__ float d_const[NCONST];
__device__ float q_scr[64 * NPIX];   // q scratch, [o][pix]

// Q-kernel smem layout (floats)
#define QS_QWS  0
#define QS_QWPE 4096
#define QS_QB   12288
#define QS_FREQ 12352
#define QS_N    12384     // 49536 B

// AV-kernel smem layout (floats)
#define AS_KWS  0
#define AS_VWS  4096
#define AS_KB   8192
#define AS_VB   8448
#define AS_N    8704      // 34816 B

// ---------------------------------------------------------------------------
// Setup kernel: 32 blocks x 256. Bias computation: one warp per (uv,o),
// lane = frequency index j, butterfly reduction.
// ---------------------------------------------------------------------------
__global__ void iw_setup_kernel(const float* __restrict__ qw, const float* __restrict__ qb,
                                const float* __restrict__ kw, const float* __restrict__ kb,
                                const float* __restrict__ vw, const float* __restrict__ vb)
{
    const int g = blockIdx.x * 256 + threadIdx.x;      // 8192 threads total
    const float LN1E4_32 = 9.210340371976184f / 32.0f; // ln(10000)/32

    // folded weights: ws[c][o] = w[o][2c] + w[o][2c+1]
    if (g < 4096) {
        int c = g >> 6, o = g & 63;
        d_const[OFF_QWS + g] = qw[o*128 + 2*c] + qw[o*128 + 2*c + 1];
        d_const[OFF_KWS + g] = kw[o*128 + 2*c] + kw[o*128 + 2*c + 1];
        d_const[OFF_VWS + g] = vw[o*128 + 2*c] + vw[o*128 + 2*c + 1];
    }

    // PE-rearranged q weights: [j][t4][o], t4: 0=sin_y,1=cos_y,2=sin_x,3=cos_x
    {
        int j = g >> 8, r = g & 255, t4 = r >> 6, o = r & 63;
        int col = (t4 < 2) ? (2*j + t4) : (64 + 2*j + (t4 - 2));
        d_const[OFF_QWPE + g] = qw[o*128 + col];
    }

    if (g < 32) d_const[OFF_FREQ + g] = __expf(-(float)g * LN1E4_32);
    if (g < 64) d_const[OFF_QB + g]   = qb[g];

    // window-PE biases: warp W = (uv,o); lane j = frequency.
    const float SW = (float)(2.0 * M_PI / (1.0 + 1e-6));
    int W = g >> 5, j = g & 31;                        // W in [0,256)
    int uv = W >> 6, o = W & 63;
    float uu = (float)(uv >> 1), vv = (float)(uv & 1);
    float f = __expf(-(float)j * LN1E4_32);
    float syv, cyv, sxv, cxv;
    __sincosf(uu * SW * f, &syv, &cyv);
    __sincosf(vv * SW * f, &sxv, &cxv);
    float aK = syv*kw[o*128+2*j] + cyv*kw[o*128+2*j+1]
             + sxv*kw[o*128+64+2*j] + cxv*kw[o*128+64+2*j+1];
    float aV = syv*vw[o*128+2*j] + cyv*vw[o*128+2*j+1]
             + sxv*vw[o*128+64+2*j] + cxv*vw[o*128+64+2*j+1];
    #pragma unroll
    for (int s = 16; s > 0; s >>= 1) {
        aK += __shfl_xor_sync(0xffffffffu, aK, s);
        aV += __shfl_xor_sync(0xffffffffu, aV, s);
    }
    if (j == 0) {
        d_const[OFF_KB + W] = aK + kb[o];
        d_const[OFF_VB + W] = aV + vb[o];
    }
}

// ---------------------------------------------------------------------------
// Q kernel: q = folded-curr matvec + PE matvec + bias, packed f32x2 with
// LDS.128 weight loads (2 fma2 per smem load).
// ---------------------------------------------------------------------------
__global__ void __launch_bounds__(256, 2) iw_q_kernel(
    const float* __restrict__ curr, const float* __restrict__ flow)
{
    extern __shared__ float sm[];
    for (int i = threadIdx.x; i < 4096; i += 256) sm[QS_QWS  + i] = d_const[OFF_QWS  + i];
    for (int i = threadIdx.x; i < 8192; i += 256) sm[QS_QWPE + i] = d_const[OFF_QWPE + i];
    if (threadIdx.x < 64) sm[QS_QB   + threadIdx.x] = d_const[OFF_QB   + threadIdx.x];
    if (threadIdx.x < 32) sm[QS_FREQ + threadIdx.x] = d_const[OFF_FREQ + threadIdx.x];
    __syncthreads();

    const float* s_qws  = sm + QS_QWS;
    const float* s_qwpe = sm + QS_QWPE;
    const float* s_fr   = sm + QS_FREQ;

    int pix = blockIdx.x * 256 + threadIdx.x;
    int b   = pix >> 16;
    int rem = pix & 65535;
    int yy  = rem >> 8;
    int xx  = rem & 255;

    float2 fl = reinterpret_cast<const float2*>(flow)[pix];
    float gy = (float)yy + fl.y;
    float gx = (float)xx + fl.x;
    float dy = gy - floorf(gy);
    float dx = gx - floorf(gx);

    const float* currB = curr + b*(CH*HWX) + yy*WW + xx;

    u64t q2[32];
    const u64t* qb2 = reinterpret_cast<const u64t*>(sm + QS_QB);
    #pragma unroll
    for (int i = 0; i < 32; i++) q2[i] = qb2[i];

    #pragma unroll 4
    for (int c = 0; c < 64; c++) {
        float fc = __ldg(currB + c*HWX);
        u64t fc2 = pk2(fc, fc);
        const ulonglong2* wc4 = reinterpret_cast<const ulonglong2*>(s_qws + c*64);
        #pragma unroll
        for (int i = 0; i < 16; i++) {
            ulonglong2 w = wc4[i];
            q2[2*i]   = ffma2(fc2, w.x, q2[2*i]);
            q2[2*i+1] = ffma2(fc2, w.y, q2[2*i+1]);
        }
    }

    const float PE2 = (float)(2.0 * M_PI / (2.0 + 1e-6));  // card = (U,V) = (2,2)
    float ay = dy * PE2, ax = dx * PE2;
    #pragma unroll 2
    for (int j = 0; j < 32; j++) {
        float f = s_fr[j];
        float syv, cyv, sxv, cxv;
        __sincosf(ay * f, &syv, &cyv);
        __sincosf(ax * f, &sxv, &cxv);
        u64t sy2 = pk2(syv, syv), cy2 = pk2(cyv, cyv);
        u64t sx2 = pk2(sxv, sxv), cx2 = pk2(cxv, cxv);
        const ulonglong2* wy4 = reinterpret_cast<const ulonglong2*>(s_qwpe + j*256);
        const ulonglong2* wx4 = reinterpret_cast<const ulonglong2*>(s_qwpe + j*256 + 128);
        #pragma unroll
        for (int i = 0; i < 16; i++) {
            ulonglong2 wsy = wy4[i];          // sin_y weights (pairs)
            ulonglong2 wcy = wy4[16 + i];     // cos_y weights
            ulonglong2 wsx = wx4[i];          // sin_x weights
            ulonglong2 wcx = wx4[16 + i];     // cos_x weights
            u64t a0 = q2[2*i], a1 = q2[2*i+1];
            a0 = ffma2(sy2, wsy.x, a0);  a1 = ffma2(sy2, wsy.y, a1);
            a0 = ffma2(cy2, wcy.x, a0);  a1 = ffma2(cy2, wcy.y, a1);
            a0 = ffma2(sx2, wsx.x, a0);  a1 = ffma2(sx2, wsx.y, a1);
            a0 = ffma2(cx2, wcx.x, a0);  a1 = ffma2(cx2, wcx.y, a1);
            q2[2*i] = a0; q2[2*i+1] = a1;
        }
    }

    #pragma unroll
    for (int i = 0; i < 32; i++) {
        float lo, hi; upk2(lo, hi, q2[i]);
        q_scr[(2*i)*NPIX + pix]     = lo;
        q_scr[(2*i + 1)*NPIX + pix] = hi;
    }
}

// ---------------------------------------------------------------------------
// AV kernel: coalesced scalar gather (c-major supp) + attn + softmax + value,
// packed f32x2 with LDS.128 weight loads.
// ---------------------------------------------------------------------------
__global__ void __launch_bounds__(128, 3) iw_av_kernel(
    const float* __restrict__ supp, const float* __restrict__ flow,
    float* __restrict__ out)
{
    extern __shared__ float sm[];
    for (int i = threadIdx.x; i < 4096; i += 128) {
        sm[AS_KWS + i] = d_const[OFF_KWS + i];
        sm[AS_VWS + i] = d_const[OFF_VWS + i];
    }
    for (int i = threadIdx.x; i < 256; i += 128) {
        sm[AS_KB + i] = d_const[OFF_KB + i];
        sm[AS_VB + i] = d_const[OFF_VB + i];
    }
    __syncthreads();

    const float* s_kws = sm + AS_KWS;
    const float* s_vws = sm + AS_VWS;
    const float* s_kb  = sm + AS_KB;
    const float* s_vb  = sm + AS_VB;

    int pix = blockIdx.x * 128 + threadIdx.x;
    int b   = pix >> 16;
    int rem = pix & 65535;
    int yy  = rem >> 8;
    int xx  = rem & 255;

    float2 fl = reinterpret_cast<const float2*>(flow)[pix];
    float gy = (float)yy + fl.y;
    float gx = (float)xx + fl.x;
    int iy = (int)floorf(gy), ix = (int)floorf(gx);
    int r0 = min(max(iy,     0), HH-1);
    int r1 = min(max(iy + 1, 0), HH-1);
    int c0 = min(max(ix,     0), WW-1);
    int c1 = min(max(ix + 1, 0), WW-1);
    int o00 = r0*WW + c0, o01 = r0*WW + c1;
    int o10 = r1*WW + c0, o11 = r1*WW + c1;

    const float* suppB = supp + b*(CH*HWX);

    // load q packed (pairs over o)
    u64t q2[32];
    #pragma unroll
    for (int i = 0; i < 32; i++)
        q2[i] = pk2(q_scr[(2*i)*NPIX + pix], q_scr[(2*i + 1)*NPIX + pix]);

    // -------- attn init: packed bias-dot q . kb[u] --------
    u64t A01[8], A23[8];
    #pragma unroll
    for (int h = 0; h < 8; h++) {
        float av[4];
        #pragma unroll
        for (int u = 0; u < 4; u++) {
            const ulonglong2* kb4 = reinterpret_cast<const ulonglong2*>(s_kb + u*64);
            ulonglong2 wa = kb4[h*2], wb = kb4[h*2 + 1];
            u64t d2 = fmul2(q2[h*4], wa.x);
            d2 = ffma2(q2[h*4+1], wa.y, d2);
            d2 = ffma2(q2[h*4+2], wb.x, d2);
            d2 = ffma2(q2[h*4+3], wb.y, d2);
            float lo, hi; upk2(lo, hi, d2);
            av[u] = lo + hi;
        }
        A01[h] = pk2(av[0], av[1]);
        A23[h] = pk2(av[2], av[3]);
    }

    // -------- attn logits: folded qk dot over coalesced gather --------
    for (int ch = 0; ch < 8; ch++) {
        float f00[8], f01[8], f10[8], f11[8];
        #pragma unroll
        for (int cc = 0; cc < 8; cc++) {
            const float* p = suppB + (ch*8 + cc)*HWX;
            f00[cc] = __ldg(p + o00);
            f01[cc] = __ldg(p + o01);
            f10[cc] = __ldg(p + o10);
            f11[cc] = __ldg(p + o11);
        }
        #pragma unroll
        for (int cc = 0; cc < 8; cc++) {
            const ulonglong2* wc4 = reinterpret_cast<const ulonglong2*>(s_kws + (ch*8 + cc)*64);
            u64t F01 = pk2(f00[cc], f01[cc]);
            u64t F23 = pk2(f10[cc], f11[cc]);
            #pragma unroll
            for (int h = 0; h < 8; h++) {
                ulonglong2 wa = wc4[h*2], wb = wc4[h*2 + 1];
                u64t d2 = fmul2(q2[h*4], wa.x);
                d2 = ffma2(q2[h*4+1], wa.y, d2);
                d2 = ffma2(q2[h*4+2], wb.x, d2);
                d2 = ffma2(q2[h*4+3], wb.y, d2);
                float lo, hi; upk2(lo, hi, d2);
                float qk = lo + hi;
                u64t qk2 = pk2(qk, qk);
                A01[h] = ffma2(qk2, F01, A01[h]);
                A23[h] = ffma2(qk2, F23, A23[h]);
            }
        }
    }

    // -------- softmax over the 4 window positions (scale = 8^-0.5) --------
    const float SC = 0.35355339059327376f;
    float attn[8][4];
    #pragma unroll
    for (int h = 0; h < 8; h++) {
        float a0, a1, a2, a3;
        upk2(a0, a1, A01[h]);
        upk2(a2, a3, A23[h]);
        float m = fmaxf(fmaxf(a0, a1), fmaxf(a2, a3));
        float p0 = __expf((a0 - m) * SC);
        float p1 = __expf((a1 - m) * SC);
        float p2 = __expf((a2 - m) * SC);
        float p3 = __expf((a3 - m) * SC);
        float inv = __fdividef(1.0f, p0 + p1 + p2 + p3);
        attn[h][0] = p0*inv; attn[h][1] = p1*inv;
        attn[h][2] = p2*inv; attn[h][3] = p3*inv;
        A01[h] = pk2(attn[h][0], attn[h][1]);
        A23[h] = pk2(attn[h][2], attn[h][3]);
    }

    // -------- output: g-fold over second gather pass (L1-hit reloads) --------
    u64t out2[32];
    #pragma unroll
    for (int i = 0; i < 32; i++) out2[i] = 0ULL;

    for (int ch = 0; ch < 8; ch++) {
        float f00[8], f01[8], f10[8], f11[8];
        #pragma unroll
        for (int cc = 0; cc < 8; cc++) {
            const float* p = suppB + (ch*8 + cc)*HWX;
            f00[cc] = __ldg(p + o00);
            f01[cc] = __ldg(p + o01);
            f10[cc] = __ldg(p + o10);
            f11[cc] = __ldg(p + o11);
        }
        #pragma unroll
        for (int cc = 0; cc < 8; cc++) {
            const ulonglong2* wc4 = reinterpret_cast<const ulonglong2*>(s_vws + (ch*8 + cc)*64);
            u64t F01 = pk2(f00[cc], f01[cc]);
            u64t F23 = pk2(f10[cc], f11[cc]);
            u64t gv2[8];
            #pragma unroll
            for (int h = 0; h < 8; h++) {
                u64t g2 = fmul2(A01[h], F01);
                g2 = ffma2(A23[h], F23, g2);
                float lo, hi; upk2(lo, hi, g2);
                float gv = lo + hi;
                gv2[h] = pk2(gv, gv);
            }
            #pragma unroll
            for (int i = 0; i < 16; i++) {
                ulonglong2 w = wc4[i];
                out2[2*i]   = ffma2(gv2[i >> 1], w.x, out2[2*i]);
                out2[2*i+1] = ffma2(gv2[i >> 1], w.y, out2[2*i+1]);
            }
        }
    }

    // v pe-bias term + store
    float* outB = out + b*(CH*HWX) + yy*WW + xx;
    #pragma unroll
    for (int i = 0; i < 32; i++) {
        float lo, hi; upk2(lo, hi, out2[i]);
        int o0 = 2*i, o1 = 2*i + 1;
        int h = o0 >> 3;
        #pragma unroll
        for (int u = 0; u < 4; u++) {
            lo = fmaf(attn[h][u], s_vb[u*64 + o0], lo);
            hi = fmaf(attn[h][u], s_vb[u*64 + o1], hi);
        }
        outB[o0*HWX] = lo;
        outB[o1*HWX] = hi;
    }
}

// ---------------------------------------------------------------------------
extern "C" void kernel_launch(void* const* d_in, const int* in_sizes, int n_in,
                              void* d_out, int out_size)
{
    const float* supp = (const float*)d_in[0];
    const float* flow = (const float*)d_in[1];
    const float* curr = (const float*)d_in[2];
    const float* qw   = (const float*)d_in[3];
    const float* qb   = (const float*)d_in[4];
    const float* kw   = (const float*)d_in[5];
    const float* kb   = (const float*)d_in[6];
    const float* vw   = (const float*)d_in[7];
    const float* vb   = (const float*)d_in[8];
    float* outp = (float*)d_out;

    cudaFuncSetAttribute(iw_q_kernel,
                         cudaFuncAttributeMaxDynamicSharedMemorySize, QS_N * 4);
    cudaFuncSetAttribute(iw_av_kernel,
                         cudaFuncAttributeMaxDynamicSharedMemorySize, AS_N * 4);

    iw_setup_kernel<<<32, 256>>>(qw, qb, kw, kb, vw, vb);
    iw_q_kernel<<<NPIX / 256, 256, QS_N * 4>>>(curr, flow);
    iw_av_kernel<<<NPIX / 128, 128, AS_N * 4>>>(supp, flow, outp);
}